// round 14
// baseline (speedup 1.0000x reference)
#include <cuda_runtime.h>
#include <math_constants.h>
#include <cstddef>

// Problem constants (fixed shapes)
#define NTOT   32768
#define NPB    16384
#define BB     2
#define MPB    4096
#define MTOT   (BB*MPB)        // 8192
#define KNN_K  16
#define CIN    64
#define COUT   128
#define NP_SZ  (MTOT*3)
#define NX_SZ  (MTOT*COUT)
#define KSEG   16
#define SEGN   (NPB/KSEG)      // 1024
#define NCH    2048            // fps: 8-point chunks per batch

// Scratch (device globals; no allocation allowed)
__device__ float4 g_p4[NTOT];
__device__ int    g_knn[MTOT*KNN_K];
__device__ int    g_sortidx[NTOT];
__device__ float  g_kd[MTOT*KSEG*KNN_K];
__device__ int    g_ki[MTOT*KSEG*KNN_K];

// ---------------------------------------------------------------------------
// Kernel 1: precompute point norms for KNN; write n_o outputs.
// ---------------------------------------------------------------------------
__global__ void prep_kernel(const float* __restrict__ p, float* __restrict__ out) {
    int i = blockIdx.x * blockDim.x + threadIdx.x;
    if (i < NTOT) {
        float px = p[3*i+0], py = p[3*i+1], pz = p[3*i+2];
        float pn = (px*px + py*py) + pz*pz;
        g_p4[i] = make_float4(px, py, pz, pn);
    }
    if (i == 0) {
        out[NP_SZ + NX_SZ + 0] = (float)MPB;
        out[NP_SZ + NX_SZ + 1] = (float)(2*MPB);
    }
}

// ---------------------------------------------------------------------------
// Kernel 1b: Morton sort (bitonic in SMEM), one CTA per batch.
// ---------------------------------------------------------------------------
__device__ __forceinline__ unsigned spread3(unsigned v) {
    v &= 0x3FFu;
    v = (v | (v << 16)) & 0x030000FFu;
    v = (v | (v << 8))  & 0x0300F00Fu;
    v = (v | (v << 4))  & 0x030C30C3u;
    v = (v | (v << 2))  & 0x09249249u;
    return v;
}

extern __shared__ unsigned sort_sm[];

__global__ __launch_bounds__(1024, 1)
void sort_kernel(const float* __restrict__ p) {
    unsigned* keys = sort_sm;
    __shared__ float smn[3][32], smx[3][32];
    __shared__ float s_mn[3], s_sc[3];

    const int b = blockIdx.x, t = threadIdx.x;
    const int lane = t & 31, warp = t >> 5;
    const float* pb = p + (size_t)b * NPB * 3;

    float mn[3] = { CUDART_INF_F,  CUDART_INF_F,  CUDART_INF_F};
    float mx[3] = {-CUDART_INF_F, -CUDART_INF_F, -CUDART_INF_F};
    #pragma unroll
    for (int j = 0; j < 16; ++j) {
        int pos = t + j*1024;
        #pragma unroll
        for (int d = 0; d < 3; ++d) {
            float v = pb[3*pos+d];
            mn[d] = fminf(mn[d], v); mx[d] = fmaxf(mx[d], v);
        }
    }
    #pragma unroll
    for (int d = 0; d < 3; ++d) {
        #pragma unroll
        for (int o = 16; o; o >>= 1) {
            mn[d] = fminf(mn[d], __shfl_xor_sync(0xffffffffu, mn[d], o));
            mx[d] = fmaxf(mx[d], __shfl_xor_sync(0xffffffffu, mx[d], o));
        }
        if (lane == 0) { smn[d][warp] = mn[d]; smx[d][warp] = mx[d]; }
    }
    __syncthreads();
    if (warp == 0) {
        #pragma unroll
        for (int d = 0; d < 3; ++d) {
            float a = smn[d][lane], c = smx[d][lane];
            #pragma unroll
            for (int o = 16; o; o >>= 1) {
                a = fminf(a, __shfl_xor_sync(0xffffffffu, a, o));
                c = fmaxf(c, __shfl_xor_sync(0xffffffffu, c, o));
            }
            if (lane == 0) {
                s_mn[d] = a;
                s_sc[d] = 63.999f / fmaxf(c - a, 1e-12f);
            }
        }
    }
    __syncthreads();
    const float mnx = s_mn[0], mny = s_mn[1], mnz = s_mn[2];
    const float scx = s_sc[0], scy = s_sc[1], scz = s_sc[2];

    #pragma unroll
    for (int j = 0; j < 16; ++j) {
        int pos = t + j*1024;
        unsigned cx = (unsigned)min(63, max(0, (int)((pb[3*pos+0]-mnx)*scx)));
        unsigned cy = (unsigned)min(63, max(0, (int)((pb[3*pos+1]-mny)*scy)));
        unsigned cz = (unsigned)min(63, max(0, (int)((pb[3*pos+2]-mnz)*scz)));
        unsigned code = spread3(cx) | (spread3(cy) << 1) | (spread3(cz) << 2);
        keys[pos] = (code << 14) | (unsigned)pos;
    }
    __syncthreads();

    for (int k = 2; k <= NPB; k <<= 1) {
        for (int j = k >> 1; j > 0; j >>= 1) {
            #pragma unroll
            for (int q = 0; q < NPB/2/1024; ++q) {
                int t2 = t + q*1024;
                int i  = 2*t2 - (t2 & (j-1));
                int ix = i + j;
                bool up = ((i & k) == 0);
                unsigned a = keys[i], c = keys[ix];
                if ((a > c) == up) { keys[i] = c; keys[ix] = a; }
            }
            __syncthreads();
        }
    }

    #pragma unroll
    for (int j = 0; j < 16; ++j) {
        int pos = t + j*1024;
        g_sortidx[b*NPB + pos] = (int)(keys[pos] & 0x3FFFu);
    }
}

// ---------------------------------------------------------------------------
// Kernel 2: FPS with exact chunk pruning, 8-POINT chunks (2048/batch).
// Thread t owns chunks qa = permA[t] (from 0..1023) and qb = permB[t]
// (from 1024..2047). Per chunk: sphere/threshold/cached u64 key in regs;
// dist[0..7] for qa, dist[8..15] for qb. Tail chunks (radius > 1.5*mean,
// per half) packed to low slots = low warps. Coords float2(x,y)+z in
// transposed SMEM (addr = (pos&7)*2048 + (pos>>3)); sid pre-flipped.
// Two-pass rescan (validated R12). Selection rule identical -> bit-exact.
// ---------------------------------------------------------------------------
extern __shared__ float fps_sm[];

__global__ __launch_bounds__(1024, 1)
void fps_kernel(const float* __restrict__ p, float* __restrict__ out) {
    float2* sxy = (float2*)fps_sm;                          // 128 KB
    float*  sz  = fps_sm + 2*NPB;                           // 64 KB
    unsigned short* sid = (unsigned short*)(fps_sm + 3*NPB);// 32 KB
    int* scratch = (int*)(fps_sm + 3*NPB);      // overlays sid[0..4095]

    __shared__ unsigned long long s_k[2][32];
    __shared__ float s_wsum[32];
    __shared__ int   s_wcnt[32];
    __shared__ int   s_woff[32];
    __shared__ float s_theta;
    __shared__ int   s_B;

    const int b = blockIdx.x, t = threadIdx.x;
    const int lane = t & 31, warp = t >> 5;
    const float* pb = p + (size_t)b * NPB * 3;
    const int* sidg = g_sortidx + b*NPB;

    // 1. coords into transposed SMEM: pos -> addr (pos&7)*2048 + (pos>>3)
    #pragma unroll
    for (int j = 0; j < 16; ++j) {
        int pos = t + j*1024;
        int oi  = sidg[pos];
        int addr = (pos & 7)*2048 + (pos >> 3);
        sxy[addr] = make_float2(pb[3*oi+0], pb[3*oi+1]);
        sz[addr]  = pb[3*oi+2];
    }
    if (t == 0) {
        float* orow = out + (size_t)b * MPB * 3;
        orow[0] = pb[0]; orow[1] = pb[1]; orow[2] = pb[2];
    }
    __syncthreads();

    // 2. radii of ALIGNED chunks t and 1024+t
    float rA, rB;
    {
        #pragma unroll
        for (int h = 0; h < 2; ++h) {
            int c = t + h*1024;
            float mnx = CUDART_INF_F, mny = CUDART_INF_F, mnz = CUDART_INF_F;
            float mxx = -CUDART_INF_F, mxy = -CUDART_INF_F, mxz = -CUDART_INF_F;
            #pragma unroll
            for (int j = 0; j < 8; ++j) {
                int addr = j*2048 + c;
                float2 xy = sxy[addr];
                float z = sz[addr];
                mnx = fminf(mnx, xy.x); mxx = fmaxf(mxx, xy.x);
                mny = fminf(mny, xy.y); mxy = fmaxf(mxy, xy.y);
                mnz = fminf(mnz, z);    mxz = fmaxf(mxz, z);
            }
            float ax = 0.5f*(mnx+mxx), ay = 0.5f*(mny+mxy), az = 0.5f*(mnz+mxz);
            float r2 = 0.0f;
            #pragma unroll
            for (int j = 0; j < 8; ++j) {
                int addr = j*2048 + c;
                float2 xy = sxy[addr];
                float dx = xy.x-ax, dy = xy.y-ay, dz = sz[addr]-az;
                r2 = fmaxf(r2, dx*dx + dy*dy + dz*dz);
            }
            if (h == 0) rA = sqrtf(r2); else rB = sqrtf(r2);
        }
    }
    // mean radius over 2048 chunks -> theta
    {
        float rs = rA + rB;
        #pragma unroll
        for (int o = 16; o; o >>= 1) rs += __shfl_xor_sync(0xffffffffu, rs, o);
        if (lane == 0) s_wsum[warp] = rs;
    }
    __syncthreads();
    if (warp == 0) {
        float v = s_wsum[lane];
        #pragma unroll
        for (int o = 16; o; o >>= 1) v += __shfl_xor_sync(0xffffffffu, v, o);
        if (lane == 0) s_theta = 1.5f * (v * (1.0f/2048.0f));
    }
    __syncthreads();

    // 3. stable partitions (hot -> low slots), half A then half B
    int qa, qb;
    #pragma unroll
    for (int h = 0; h < 2; ++h) {
        float rt = (h == 0) ? rA : rB;
        bool big = rt > s_theta;
        unsigned wb = __ballot_sync(0xffffffffu, big);
        if (lane == 0) s_wcnt[warp] = __popc(wb);
        __syncthreads();
        if (warp == 0) {
            int c = s_wcnt[lane];
            int inc = c;
            #pragma unroll
            for (int o = 1; o < 32; o <<= 1) {
                int n = __shfl_up_sync(0xffffffffu, inc, o);
                if (lane >= o) inc += n;
            }
            s_woff[lane] = inc - c;
            if (lane == 31) s_B = inc;
        }
        __syncthreads();
        int before = s_woff[warp] + __popc(wb & ((1u << lane) - 1u));
        int slot = big ? before : (s_B + (t - before));
        scratch[h*1024 + slot] = t + h*1024;
        __syncthreads();
        if (h == 0) qa = scratch[t]; else qb = scratch[1024 + t];
        __syncthreads();
    }

    // 4. fill sid with PRE-FLIPPED original index (overwrites scratch:
    //    scratch used sid addrs 0..4095 <-> pos = 8c + jj, jj in {0,1})
    #pragma unroll
    for (int j = 0; j < 16; ++j) {
        int pos = t + j*1024;
        int addr = (pos & 7)*2048 + (pos >> 3);
        sid[addr] = (unsigned short)(sidg[pos] ^ 0x3FFF);
    }
    __syncthreads();

    // 5. spheres for chunks qa, qb
    float aC0x, aC0y, aC0z, aR, bC0x, bC0y, bC0z, bR;
    #pragma unroll
    for (int h = 0; h < 2; ++h) {
        int c = (h == 0) ? qa : qb;
        float mnx = CUDART_INF_F, mny = CUDART_INF_F, mnz = CUDART_INF_F;
        float mxx = -CUDART_INF_F, mxy = -CUDART_INF_F, mxz = -CUDART_INF_F;
        #pragma unroll
        for (int j = 0; j < 8; ++j) {
            int addr = j*2048 + c;
            float2 xy = sxy[addr];
            float z = sz[addr];
            mnx = fminf(mnx, xy.x); mxx = fmaxf(mxx, xy.x);
            mny = fminf(mny, xy.y); mxy = fmaxf(mxy, xy.y);
            mnz = fminf(mnz, z);    mxz = fmaxf(mxz, z);
        }
        float c0x = 0.5f*(mnx+mxx), c0y = 0.5f*(mny+mxy), c0z = 0.5f*(mnz+mxz);
        float r2 = 0.0f;
        #pragma unroll
        for (int j = 0; j < 8; ++j) {
            int addr = j*2048 + c;
            float2 xy = sxy[addr];
            float dx = xy.x-c0x, dy = xy.y-c0y, dz = sz[addr]-c0z;
            r2 = fmaxf(r2, dx*dx + dy*dy + dz*dz);
        }
        float r = sqrtf(r2) * 1.0002f + 1e-12f;
        if (h == 0) { aC0x=c0x; aC0y=c0y; aC0z=c0z; aR=r; }
        else        { bC0x=c0x; bC0y=c0y; bC0z=c0z; bR=r; }
    }

    float dist[16];
    #pragma unroll
    for (int j = 0; j < 16; ++j) dist[j] = CUDART_INF_F;

    unsigned long long keyA =
        ((unsigned long long)__float_as_uint(CUDART_INF_F) << 32) | (unsigned)(qa << 3);
    unsigned long long keyB =
        ((unsigned long long)__float_as_uint(CUDART_INF_F) << 32) | (unsigned)(qb << 3);
    float trA = CUDART_INF_F, trB = CUDART_INF_F;
    unsigned long long wkey = 0;

    float cx = pb[0], cy = pb[1], cz = pb[2];
    const unsigned qaBase = (unsigned)(qa << 3);
    const unsigned qbBase = (unsigned)(qb << 3);

    for (int i = 1; i < MPB; ++i) {
        float dax = cx - aC0x, day = cy - aC0y, daz = cz - aC0z;
        bool actA = !((dax*dax + day*day + daz*daz) > trA);
        float dbx = cx - bC0x, dby = cy - bC0y, dbz = cz - bC0z;
        bool actB = !((dbx*dbx + dby*dby + dbz*dbz) > trB);

        if (actA) {
            float nm = -CUDART_INF_F;
            #pragma unroll
            for (int j = 0; j < 8; ++j) {
                int addr = j*2048 + qa;
                float2 xy = sxy[addr];
                float dx = xy.x - cx;
                float dy = xy.y - cy;
                float dz = sz[addr] - cz;
                float d = __fadd_rn(__fadd_rn(__fmul_rn(dx,dx), __fmul_rn(dy,dy)),
                                    __fmul_rn(dz,dz));
                float nd = fminf(dist[j], d);
                dist[j] = nd;
                nm = fmaxf(nm, nd);
            }
            unsigned lkbest = 0u;
            #pragma unroll
            for (int j = 0; j < 8; ++j) {
                if (dist[j] == nm) {
                    int addr = j*2048 + qa;
                    unsigned lk = ((unsigned)sid[addr] << 14) | (qaBase + (unsigned)j);
                    lkbest = max(lkbest, lk);
                }
            }
            keyA = ((unsigned long long)__float_as_uint(nm) << 32) | lkbest;
            float rr = aR + sqrtf(nm);
            trA = rr*rr*1.0002f;
        }
        if (actB) {
            float nm = -CUDART_INF_F;
            #pragma unroll
            for (int j = 0; j < 8; ++j) {
                int addr = j*2048 + qb;
                float2 xy = sxy[addr];
                float dx = xy.x - cx;
                float dy = xy.y - cy;
                float dz = sz[addr] - cz;
                float d = __fadd_rn(__fadd_rn(__fmul_rn(dx,dx), __fmul_rn(dy,dy)),
                                    __fmul_rn(dz,dz));
                float nd = fminf(dist[8+j], d);
                dist[8+j] = nd;
                nm = fmaxf(nm, nd);
            }
            unsigned lkbest = 0u;
            #pragma unroll
            for (int j = 0; j < 8; ++j) {
                if (dist[8+j] == nm) {
                    int addr = j*2048 + qb;
                    unsigned lk = ((unsigned)sid[addr] << 14) | (qbBase + (unsigned)j);
                    lkbest = max(lkbest, lk);
                }
            }
            keyB = ((unsigned long long)__float_as_uint(nm) << 32) | lkbest;
            float rr = bR + sqrtf(nm);
            trB = rr*rr*1.0002f;
        }
        if (__ballot_sync(0xffffffffu, actA || actB)) {
            unsigned long long mykey = (keyA > keyB) ? keyA : keyB;
            unsigned hi = (unsigned)(mykey >> 32);
            unsigned lo = (unsigned)mykey;
            unsigned hm = __reduce_max_sync(0xffffffffu, hi);
            unsigned cd = (hi == hm) ? lo : 0u;
            unsigned lm = __reduce_max_sync(0xffffffffu, cd);
            wkey = ((unsigned long long)hm << 32) | lm;
        }
        if (lane == 0)
            s_k[i & 1][warp] = wkey;
        __syncthreads();

        unsigned long long kk = s_k[i & 1][lane];
        unsigned h2  = (unsigned)(kk >> 32);
        unsigned lo2 = (unsigned)kk;
        unsigned hb  = __reduce_max_sync(0xffffffffu, h2);
        unsigned c2  = (h2 == hb) ? lo2 : 0u;
        unsigned lob = __reduce_max_sync(0xffffffffu, c2);
        int wpos = (int)(lob & 0x3FFFu);
        int waddr = (wpos & 7)*2048 + (wpos >> 3);
        float2 wxy = sxy[waddr];
        cx = wxy.x; cy = wxy.y; cz = sz[waddr];
        if (t == 0) {
            float* orow = out + ((size_t)b * MPB + i) * 3;
            orow[0] = cx; orow[1] = cy; orow[2] = cz;
        }
    }
}

// ---------------------------------------------------------------------------
// Kernel 3a: segmented KNN (top-16 per 1024-pt segment per query).
// ---------------------------------------------------------------------------
__global__ __launch_bounds__(128)
void knn_part(const float* __restrict__ out_np) {
    __shared__ float4 tile[SEGN];
    const int m = blockIdx.x * 128 + threadIdx.x;
    const int s = blockIdx.y;
    const int b = m >> 12;
    const int base = (b << 14) + s * SEGN;

    const float qx = out_np[3*m+0];
    const float qy = out_np[3*m+1];
    const float qz = out_np[3*m+2];
    const float qn = (qx*qx + qy*qy) + qz*qz;

    #pragma unroll
    for (int i = 0; i < SEGN/128; ++i)
        tile[threadIdx.x + i*128] = g_p4[base + threadIdx.x + i*128];
    __syncthreads();

    float bd[KNN_K];
    int   bi[KNN_K];
    #pragma unroll
    for (int k = 0; k < KNN_K; ++k) { bd[k] = CUDART_INF_F; bi[k] = 0x7FFFFFFF; }

    #pragma unroll 4
    for (int tt = 0; tt < SEGN; ++tt) {
        float4 pp = tile[tt];
        float dot = qx*pp.x + qy*pp.y + qz*pp.z;
        float d2  = fmaf(-2.0f, dot, qn + pp.w);
        if (d2 < bd[KNN_K-1]) {
            bd[KNN_K-1] = d2; bi[KNN_K-1] = s*SEGN + tt;
            #pragma unroll
            for (int k = KNN_K-1; k > 0; --k) {
                if (bd[k] < bd[k-1]) {
                    float td = bd[k]; bd[k] = bd[k-1]; bd[k-1] = td;
                    int   ti = bi[k]; bi[k] = bi[k-1]; bi[k-1] = ti;
                }
            }
        }
    }
    float* od = g_kd + ((size_t)m*KSEG + s) * KNN_K;
    int*   oi = g_ki + ((size_t)m*KSEG + s) * KNN_K;
    #pragma unroll
    for (int k = 0; k < KNN_K; ++k) { od[k] = bd[k]; oi[k] = bi[k]; }
}

// ---------------------------------------------------------------------------
// Kernel 3b: 16-way merge of sorted per-segment lists.
// ---------------------------------------------------------------------------
__global__ __launch_bounds__(128)
void knn_merge() {
    const int m = blockIdx.x * 128 + threadIdx.x;
    const float* dsrc = g_kd + (size_t)m * KSEG * KNN_K;
    const int*   isrc = g_ki + (size_t)m * KSEG * KNN_K;

    int   pt[KSEG];
    float hd[KSEG];
    int   hi[KSEG];
    #pragma unroll
    for (int s = 0; s < KSEG; ++s) {
        pt[s] = 0;
        hd[s] = dsrc[s*KNN_K];
        hi[s] = isrc[s*KNN_K];
    }
    #pragma unroll
    for (int k = 0; k < KNN_K; ++k) {
        int   bs = 0;
        float bdv = hd[0];
        int   biv = hi[0];
        #pragma unroll
        for (int s = 1; s < KSEG; ++s) {
            if (hd[s] < bdv || (hd[s] == bdv && hi[s] < biv)) {
                bdv = hd[s]; biv = hi[s]; bs = s;
            }
        }
        g_knn[m*KNN_K + k] = biv;
        int np = ++pt[bs];
        if (np < KNN_K) {
            hd[bs] = dsrc[bs*KNN_K + np];
            hi[bs] = isrc[bs*KNN_K + np];
        } else {
            hd[bs] = CUDART_INF_F; hi[bs] = 0x7FFFFFFF;
        }
    }
}

// ---------------------------------------------------------------------------
// Kernel 4: gather + linear + LayerNorm + ReLU + max over K.
// ---------------------------------------------------------------------------
__global__ __launch_bounds__(256)
void head_kernel(const float* __restrict__ p, const float* __restrict__ x,
                 const float* __restrict__ W, const float* __restrict__ gamma,
                 const float* __restrict__ beta, float* __restrict__ out) {
    __shared__ __align__(16) float sW[(3+CIN)*COUT];
    __shared__ __align__(16) float sFx[8][CIN];

    const int tid  = threadIdx.x;
    const int lane = tid & 31;
    const int w    = tid >> 5;

    for (int i = tid; i < (3+CIN)*COUT; i += 256) sW[i] = W[i];

    const int m = blockIdx.x * 8 + w;
    const int b = m >> 12;
    const float* pb = p + (size_t)b * NPB * 3;
    const float* xb = x + (size_t)b * NPB * CIN;

    const float qx = out[3*m+0], qy = out[3*m+1], qz = out[3*m+2];
    const float4 gv = ((const float4*)gamma)[lane];
    const float4 bv = ((const float4*)beta)[lane];
    int myidx = g_knn[m*KNN_K + (lane & 15)];
    __syncthreads();

    float mx0 = -CUDART_INF_F, mx1 = -CUDART_INF_F,
          mx2 = -CUDART_INF_F, mx3 = -CUDART_INF_F;

    for (int k = 0; k < KNN_K; ++k) {
        int idx = __shfl_sync(0xffffffffu, myidx, k);
        float2 xv = ((const float2*)(xb + (size_t)idx * CIN))[lane];
        ((float2*)sFx[w])[lane] = xv;
        float rx = pb[3*idx+0] - qx;
        float ry = pb[3*idx+1] - qy;
        float rz = pb[3*idx+2] - qz;
        __syncwarp();

        float a0, a1, a2, a3;
        {
            float4 w0 = *(const float4*)(sW + 0*COUT + lane*4);
            float4 w1 = *(const float4*)(sW + 1*COUT + lane*4);
            float4 w2 = *(const float4*)(sW + 2*COUT + lane*4);
            a0 = rx*w0.x; a1 = rx*w0.y; a2 = rx*w0.z; a3 = rx*w0.w;
            a0 = fmaf(ry, w1.x, a0); a1 = fmaf(ry, w1.y, a1);
            a2 = fmaf(ry, w1.z, a2); a3 = fmaf(ry, w1.w, a3);
            a0 = fmaf(rz, w2.x, a0); a1 = fmaf(rz, w2.y, a1);
            a2 = fmaf(rz, w2.z, a2); a3 = fmaf(rz, w2.w, a3);
        }
        #pragma unroll
        for (int c = 0; c < CIN; ++c) {
            float f = sFx[w][c];
            float4 wv = *(const float4*)(sW + (c+3)*COUT + lane*4);
            a0 = fmaf(f, wv.x, a0); a1 = fmaf(f, wv.y, a1);
            a2 = fmaf(f, wv.z, a2); a3 = fmaf(f, wv.w, a3);
        }
        float s = (a0 + a1) + (a2 + a3);
        #pragma unroll
        for (int o = 16; o; o >>= 1) s += __shfl_xor_sync(0xffffffffu, s, o);
        float mu = s * (1.0f/128.0f);
        float t0 = a0 - mu, t1 = a1 - mu, t2 = a2 - mu, t3 = a3 - mu;
        float v = (t0*t0 + t1*t1) + (t2*t2 + t3*t3);
        #pragma unroll
        for (int o = 16; o; o >>= 1) v += __shfl_xor_sync(0xffffffffu, v, o);
        float rs = rsqrtf(v * (1.0f/128.0f) + 1e-5f);
        float h0 = fmaf(t0*rs, gv.x, bv.x);
        float h1 = fmaf(t1*rs, gv.y, bv.y);
        float h2 = fmaf(t2*rs, gv.z, bv.z);
        float h3 = fmaf(t3*rs, gv.w, bv.w);
        mx0 = fmaxf(mx0, fmaxf(h0, 0.0f));
        mx1 = fmaxf(mx1, fmaxf(h1, 0.0f));
        mx2 = fmaxf(mx2, fmaxf(h2, 0.0f));
        mx3 = fmaxf(mx3, fmaxf(h3, 0.0f));
        __syncwarp();
    }

    float4 res = make_float4(mx0, mx1, mx2, mx3);
    ((float4*)(out + NP_SZ))[(size_t)m*32 + lane] = res;
}

// ---------------------------------------------------------------------------
// Launch
// ---------------------------------------------------------------------------
extern "C" void kernel_launch(void* const* d_in, const int* in_sizes, int n_in,
                              void* d_out, int out_size) {
    const float* p     = (const float*)d_in[0];
    const float* x     = (const float*)d_in[1];
    const float* W     = (const float*)d_in[3];
    const float* gamma = (const float*)d_in[4];
    const float* beta  = (const float*)d_in[5];
    float* out = (float*)d_out;

    const int sort_smem = NPB * (int)sizeof(unsigned);                                // 64 KB
    const int fps_smem  = 3*NPB*(int)sizeof(float) + NPB*(int)sizeof(unsigned short); // 224 KB
    cudaFuncSetAttribute(sort_kernel, cudaFuncAttributeMaxDynamicSharedMemorySize, sort_smem);
    cudaFuncSetAttribute(fps_kernel,  cudaFuncAttributeMaxDynamicSharedMemorySize, fps_smem);

    prep_kernel<<<(NTOT + 255) / 256, 256>>>(p, out);
    sort_kernel<<<BB, 1024, sort_smem>>>(p);
    fps_kernel<<<BB, 1024, fps_smem>>>(p, out);
    knn_part<<<dim3(MTOT/128, KSEG), 128>>>(out);
    knn_merge<<<MTOT/128, 128>>>();
    head_kernel<<<MTOT / 8, 256>>>(p, x, W, gamma, beta, out);
}

// round 15
// speedup vs baseline: 1.2803x; 1.2803x over previous
#include <cuda_runtime.h>
#include <math_constants.h>
#include <cstddef>

// Problem constants (fixed shapes)
#define NTOT   32768
#define NPB    16384
#define BB     2
#define MPB    4096
#define MTOT   (BB*MPB)        // 8192
#define KNN_K  16
#define CIN    64
#define COUT   128
#define NP_SZ  (MTOT*3)
#define NX_SZ  (MTOT*COUT)
#define KSEG   16
#define SEGN   (NPB/KSEG)      // 1024

// Scratch (device globals; no allocation allowed)
__device__ float4 g_p4[NTOT];
__device__ int    g_knn[MTOT*KNN_K];
__device__ int    g_sortidx[NTOT];
__device__ float  g_kd[MTOT*KSEG*KNN_K];
__device__ int    g_ki[MTOT*KSEG*KNN_K];

// ---------------------------------------------------------------------------
// Kernel 1: precompute point norms for KNN; write n_o outputs.
// ---------------------------------------------------------------------------
__global__ void prep_kernel(const float* __restrict__ p, float* __restrict__ out) {
    int i = blockIdx.x * blockDim.x + threadIdx.x;
    if (i < NTOT) {
        float px = p[3*i+0], py = p[3*i+1], pz = p[3*i+2];
        float pn = (px*px + py*py) + pz*pz;
        g_p4[i] = make_float4(px, py, pz, pn);
    }
    if (i == 0) {
        out[NP_SZ + NX_SZ + 0] = (float)MPB;
        out[NP_SZ + NX_SZ + 1] = (float)(2*MPB);
    }
}

// ---------------------------------------------------------------------------
// Kernel 1b: Morton sort (bitonic in SMEM), one CTA per batch.
// ---------------------------------------------------------------------------
__device__ __forceinline__ unsigned spread3(unsigned v) {
    v &= 0x3FFu;
    v = (v | (v << 16)) & 0x030000FFu;
    v = (v | (v << 8))  & 0x0300F00Fu;
    v = (v | (v << 4))  & 0x030C30C3u;
    v = (v | (v << 2))  & 0x09249249u;
    return v;
}

extern __shared__ unsigned sort_sm[];

__global__ __launch_bounds__(1024, 1)
void sort_kernel(const float* __restrict__ p) {
    unsigned* keys = sort_sm;
    __shared__ float smn[3][32], smx[3][32];
    __shared__ float s_mn[3], s_sc[3];

    const int b = blockIdx.x, t = threadIdx.x;
    const int lane = t & 31, warp = t >> 5;
    const float* pb = p + (size_t)b * NPB * 3;

    float mn[3] = { CUDART_INF_F,  CUDART_INF_F,  CUDART_INF_F};
    float mx[3] = {-CUDART_INF_F, -CUDART_INF_F, -CUDART_INF_F};
    #pragma unroll
    for (int j = 0; j < 16; ++j) {
        int pos = t + j*1024;
        #pragma unroll
        for (int d = 0; d < 3; ++d) {
            float v = pb[3*pos+d];
            mn[d] = fminf(mn[d], v); mx[d] = fmaxf(mx[d], v);
        }
    }
    #pragma unroll
    for (int d = 0; d < 3; ++d) {
        #pragma unroll
        for (int o = 16; o; o >>= 1) {
            mn[d] = fminf(mn[d], __shfl_xor_sync(0xffffffffu, mn[d], o));
            mx[d] = fmaxf(mx[d], __shfl_xor_sync(0xffffffffu, mx[d], o));
        }
        if (lane == 0) { smn[d][warp] = mn[d]; smx[d][warp] = mx[d]; }
    }
    __syncthreads();
    if (warp == 0) {
        #pragma unroll
        for (int d = 0; d < 3; ++d) {
            float a = smn[d][lane], c = smx[d][lane];
            #pragma unroll
            for (int o = 16; o; o >>= 1) {
                a = fminf(a, __shfl_xor_sync(0xffffffffu, a, o));
                c = fmaxf(c, __shfl_xor_sync(0xffffffffu, c, o));
            }
            if (lane == 0) {
                s_mn[d] = a;
                s_sc[d] = 63.999f / fmaxf(c - a, 1e-12f);
            }
        }
    }
    __syncthreads();
    const float mnx = s_mn[0], mny = s_mn[1], mnz = s_mn[2];
    const float scx = s_sc[0], scy = s_sc[1], scz = s_sc[2];

    #pragma unroll
    for (int j = 0; j < 16; ++j) {
        int pos = t + j*1024;
        unsigned cx = (unsigned)min(63, max(0, (int)((pb[3*pos+0]-mnx)*scx)));
        unsigned cy = (unsigned)min(63, max(0, (int)((pb[3*pos+1]-mny)*scy)));
        unsigned cz = (unsigned)min(63, max(0, (int)((pb[3*pos+2]-mnz)*scz)));
        unsigned code = spread3(cx) | (spread3(cy) << 1) | (spread3(cz) << 2);
        keys[pos] = (code << 14) | (unsigned)pos;
    }
    __syncthreads();

    for (int k = 2; k <= NPB; k <<= 1) {
        for (int j = k >> 1; j > 0; j >>= 1) {
            #pragma unroll
            for (int q = 0; q < NPB/2/1024; ++q) {
                int t2 = t + q*1024;
                int i  = 2*t2 - (t2 & (j-1));
                int ix = i + j;
                bool up = ((i & k) == 0);
                unsigned a = keys[i], c = keys[ix];
                if ((a > c) == up) { keys[i] = c; keys[ix] = a; }
            }
            __syncthreads();
        }
    }

    #pragma unroll
    for (int j = 0; j < 16; ++j) {
        int pos = t + j*1024;
        g_sortidx[b*NPB + pos] = (int)(keys[pos] & 0x3FFFu);
    }
}

// ---------------------------------------------------------------------------
// Kernel 2: FPS with exact chunk pruning (R12 structure, verbatim).
// Tail chunks (radius > 1.5*mean) packed into the lowest warps; core keeps
// Morton order. Thread owns chunk q: sphere/threshold/cached key + dist[16]
// in registers. Coords as float2(x,y)+float(z) in transposed SMEM
// (addr = (pos&15)*1024 + (pos>>4)); sid stores PRE-FLIPPED original index
// (oi^0x3FFF).
// Rescan: pass 1 = dist update + fmaxf chain (no key work);
//         pass 2 = tie key only for dist[j]==nm (exact bitwise equality).
// Selection rule (dist desc, original-index asc) identical -> bit-exact.
// ---------------------------------------------------------------------------
extern __shared__ float fps_sm[];

__global__ __launch_bounds__(1024, 1)
void fps_kernel(const float* __restrict__ p, float* __restrict__ out) {
    float2* sxy = (float2*)fps_sm;                          // 128 KB
    float*  sz  = fps_sm + 2*NPB;                           // 64 KB
    unsigned short* sid = (unsigned short*)(fps_sm + 3*NPB);// 32 KB
    int* scratch = (int*)(fps_sm + 3*NPB);      // overlays sid; used pre-fill

    __shared__ unsigned long long s_k[2][32];
    __shared__ float s_wsum[32];
    __shared__ int   s_wcnt[32];
    __shared__ int   s_woff[32];
    __shared__ float s_theta;
    __shared__ int   s_B;

    const int b = blockIdx.x, t = threadIdx.x;
    const int lane = t & 31, warp = t >> 5;
    const float* pb = p + (size_t)b * NPB * 3;
    const int* sidg = g_sortidx + b*NPB;

    // 1. coords into transposed SMEM: pos -> addr (pos&15)*1024 + (pos>>4)
    #pragma unroll
    for (int j = 0; j < 16; ++j) {
        int pos = t + j*1024;
        int oi  = sidg[pos];
        int addr = (pos & 15)*1024 + (pos >> 4);
        sxy[addr] = make_float2(pb[3*oi+0], pb[3*oi+1]);
        sz[addr]  = pb[3*oi+2];
    }
    if (t == 0) {
        float* orow = out + (size_t)b * MPB * 3;
        orow[0] = pb[0]; orow[1] = pb[1]; orow[2] = pb[2];
    }
    __syncthreads();

    // 2. radius of the ALIGNED chunk t (partition decision)
    float rt;
    {
        float mnx = CUDART_INF_F, mny = CUDART_INF_F, mnz = CUDART_INF_F;
        float mxx = -CUDART_INF_F, mxy = -CUDART_INF_F, mxz = -CUDART_INF_F;
        #pragma unroll
        for (int j = 0; j < 16; ++j) {
            int addr = j*1024 + t;
            float2 xy = sxy[addr];
            float z = sz[addr];
            mnx = fminf(mnx, xy.x); mxx = fmaxf(mxx, xy.x);
            mny = fminf(mny, xy.y); mxy = fmaxf(mxy, xy.y);
            mnz = fminf(mnz, z);    mxz = fmaxf(mxz, z);
        }
        float ax = 0.5f*(mnx+mxx), ay = 0.5f*(mny+mxy), az = 0.5f*(mnz+mxz);
        float r2 = 0.0f;
        #pragma unroll
        for (int j = 0; j < 16; ++j) {
            int addr = j*1024 + t;
            float2 xy = sxy[addr];
            float dx = xy.x-ax, dy = xy.y-ay, dz = sz[addr]-az;
            r2 = fmaxf(r2, dx*dx + dy*dy + dz*dz);
        }
        rt = sqrtf(r2);
    }
    // mean radius -> theta
    {
        float rs = rt;
        #pragma unroll
        for (int o = 16; o; o >>= 1) rs += __shfl_xor_sync(0xffffffffu, rs, o);
        if (lane == 0) s_wsum[warp] = rs;
    }
    __syncthreads();
    if (warp == 0) {
        float v = s_wsum[lane];
        #pragma unroll
        for (int o = 16; o; o >>= 1) v += __shfl_xor_sync(0xffffffffu, v, o);
        if (lane == 0) s_theta = 1.5f * (v * (1.0f/1024.0f));
    }
    __syncthreads();

    // 3. partition: big chunks -> slots [0,B), core chunks keep order after
    bool big = rt > s_theta;
    unsigned wb = __ballot_sync(0xffffffffu, big);
    if (lane == 0) s_wcnt[warp] = __popc(wb);
    __syncthreads();
    if (warp == 0) {
        int c = s_wcnt[lane];
        int inc = c;
        #pragma unroll
        for (int o = 1; o < 32; o <<= 1) {
            int n = __shfl_up_sync(0xffffffffu, inc, o);
            if (lane >= o) inc += n;
        }
        s_woff[lane] = inc - c;
        if (lane == 31) s_B = inc;
    }
    __syncthreads();
    int bigsBefore = s_woff[warp] + __popc(wb & ((1u << lane) - 1u));
    int slot = big ? bigsBefore : (s_B + (t - bigsBefore));
    scratch[slot] = t;
    __syncthreads();
    const int q = scratch[t];          // chunk owned by this thread
    __syncthreads();

    // 4. fill sid with PRE-FLIPPED original index (overwrites scratch)
    #pragma unroll
    for (int j = 0; j < 16; ++j) {
        int pos = t + j*1024;
        int addr = (pos & 15)*1024 + (pos >> 4);
        sid[addr] = (unsigned short)(sidg[pos] ^ 0x3FFF);
    }
    __syncthreads();

    // 5. sphere for chunk q
    float c0x, c0y, c0z, r;
    {
        float mnx = CUDART_INF_F, mny = CUDART_INF_F, mnz = CUDART_INF_F;
        float mxx = -CUDART_INF_F, mxy = -CUDART_INF_F, mxz = -CUDART_INF_F;
        #pragma unroll
        for (int j = 0; j < 16; ++j) {
            int addr = j*1024 + q;
            float2 xy = sxy[addr];
            float z = sz[addr];
            mnx = fminf(mnx, xy.x); mxx = fmaxf(mxx, xy.x);
            mny = fminf(mny, xy.y); mxy = fmaxf(mxy, xy.y);
            mnz = fminf(mnz, z);    mxz = fmaxf(mxz, z);
        }
        c0x = 0.5f*(mnx+mxx); c0y = 0.5f*(mny+mxy); c0z = 0.5f*(mnz+mxz);
        float r2 = 0.0f;
        #pragma unroll
        for (int j = 0; j < 16; ++j) {
            int addr = j*1024 + q;
            float2 xy = sxy[addr];
            float dx = xy.x-c0x, dy = xy.y-c0y, dz = sz[addr]-c0z;
            r2 = fmaxf(r2, dx*dx + dy*dy + dz*dz);
        }
        r = sqrtf(r2) * 1.0002f + 1e-12f;
    }

    float dist[16];
    #pragma unroll
    for (int j = 0; j < 16; ++j) dist[j] = CUDART_INF_F;

    // cached chunk key (u64: distbits<<32 | lowkey). Placeholder lowkey is
    // fine: all chunks are active at i=1 (tr=INF) and overwrite it.
    unsigned long long mykey =
        ((unsigned long long)__float_as_uint(CUDART_INF_F) << 32) | (unsigned)(q << 4);
    float tr = CUDART_INF_F;               // inf => active until first rescan
    unsigned long long wkey = 0;

    float cx = pb[0], cy = pb[1], cz = pb[2];
    const unsigned qbase = (unsigned)(q << 4);

    for (int i = 1; i < MPB; ++i) {
        float ddx = cx - c0x, ddy = cy - c0y, ddz = cz - c0z;
        float L2c = ddx*ddx + ddy*ddy + ddz*ddz;
        bool active = !(L2c > tr);

        if (active) {
            // pass 1: dist update + running max (no key work)
            float nm = -CUDART_INF_F;
            #pragma unroll
            for (int j = 0; j < 16; ++j) {
                int addr = j*1024 + q;
                float2 xy = sxy[addr];
                float dx = xy.x - cx;
                float dy = xy.y - cy;
                float dz = sz[addr] - cz;
                float d = __fadd_rn(__fadd_rn(__fmul_rn(dx,dx), __fmul_rn(dy,dy)),
                                    __fmul_rn(dz,dz));
                float nd = fminf(dist[j], d);
                dist[j] = nd;
                nm = fmaxf(nm, nd);
            }
            // pass 2: tie key only where dist[j] == nm (bitwise-exact match)
            unsigned lkbest = 0u;
            #pragma unroll
            for (int j = 0; j < 16; ++j) {
                if (dist[j] == nm) {
                    int addr = j*1024 + q;
                    unsigned lk = ((unsigned)sid[addr] << 14) | (qbase + (unsigned)j);
                    lkbest = max(lkbest, lk);
                }
            }
            mykey = ((unsigned long long)__float_as_uint(nm) << 32) | lkbest;
            float rr = r + sqrtf(nm);
            tr = rr*rr*1.0002f;
        }
        if (__ballot_sync(0xffffffffu, active)) {
            unsigned hi = (unsigned)(mykey >> 32);
            unsigned lo = (unsigned)mykey;
            unsigned hm = __reduce_max_sync(0xffffffffu, hi);
            unsigned cd = (hi == hm) ? lo : 0u;
            unsigned lm = __reduce_max_sync(0xffffffffu, cd);
            wkey = ((unsigned long long)hm << 32) | lm;
        }
        if (lane == 0)
            s_k[i & 1][warp] = wkey;
        __syncthreads();

        unsigned long long kk = s_k[i & 1][lane];
        unsigned h2  = (unsigned)(kk >> 32);
        unsigned lo2 = (unsigned)kk;
        unsigned hb  = __reduce_max_sync(0xffffffffu, h2);
        unsigned c2  = (h2 == hb) ? lo2 : 0u;
        unsigned lob = __reduce_max_sync(0xffffffffu, c2);
        int wpos = (int)(lob & 0x3FFFu);
        int waddr = (wpos & 15)*1024 + (wpos >> 4);
        float2 wxy = sxy[waddr];
        cx = wxy.x; cy = wxy.y; cz = sz[waddr];
        if (t == 0) {
            float* orow = out + ((size_t)b * MPB + i) * 3;
            orow[0] = cx; orow[1] = cy; orow[2] = cz;
        }
    }
}

// ---------------------------------------------------------------------------
// Kernel 3a: segmented KNN (top-16 per 1024-pt segment per query).
// Uses the per-query monotone transform d2' = 0.5*|p|^2 - q.p
// (= (d2 - |q|^2)/2): selection order within a query is preserved, one
// FADD per point saved. Merge consumes stored d2' consistently.
// ---------------------------------------------------------------------------
__global__ __launch_bounds__(128)
void knn_part(const float* __restrict__ out_np) {
    __shared__ float4 tile[SEGN];
    const int m = blockIdx.x * 128 + threadIdx.x;
    const int s = blockIdx.y;
    const int b = m >> 12;
    const int base = (b << 14) + s * SEGN;

    const float qx = out_np[3*m+0];
    const float qy = out_np[3*m+1];
    const float qz = out_np[3*m+2];

    #pragma unroll
    for (int i = 0; i < SEGN/128; ++i)
        tile[threadIdx.x + i*128] = g_p4[base + threadIdx.x + i*128];
    __syncthreads();

    float bd[KNN_K];
    int   bi[KNN_K];
    #pragma unroll
    for (int k = 0; k < KNN_K; ++k) { bd[k] = CUDART_INF_F; bi[k] = 0x7FFFFFFF; }

    #pragma unroll 4
    for (int tt = 0; tt < SEGN; ++tt) {
        float4 pp = tile[tt];
        float dot = qx*pp.x + qy*pp.y + qz*pp.z;
        float d2  = fmaf(0.5f, pp.w, -dot);         // transformed distance
        if (d2 < bd[KNN_K-1]) {
            bd[KNN_K-1] = d2; bi[KNN_K-1] = s*SEGN + tt;
            #pragma unroll
            for (int k = KNN_K-1; k > 0; --k) {
                if (bd[k] < bd[k-1]) {
                    float td = bd[k]; bd[k] = bd[k-1]; bd[k-1] = td;
                    int   ti = bi[k]; bi[k] = bi[k-1]; bi[k-1] = ti;
                }
            }
        }
    }
    float* od = g_kd + ((size_t)m*KSEG + s) * KNN_K;
    int*   oi = g_ki + ((size_t)m*KSEG + s) * KNN_K;
    #pragma unroll
    for (int k = 0; k < KNN_K; ++k) { od[k] = bd[k]; oi[k] = bi[k]; }
}

// ---------------------------------------------------------------------------
// Kernel 3b: 16-way merge of sorted per-segment lists (transformed d2',
// consistent across segments for the same query).
// ---------------------------------------------------------------------------
__global__ __launch_bounds__(128)
void knn_merge() {
    const int m = blockIdx.x * 128 + threadIdx.x;
    const float* dsrc = g_kd + (size_t)m * KSEG * KNN_K;
    const int*   isrc = g_ki + (size_t)m * KSEG * KNN_K;

    int   pt[KSEG];
    float hd[KSEG];
    int   hi[KSEG];
    #pragma unroll
    for (int s = 0; s < KSEG; ++s) {
        pt[s] = 0;
        hd[s] = dsrc[s*KNN_K];
        hi[s] = isrc[s*KNN_K];
    }
    #pragma unroll
    for (int k = 0; k < KNN_K; ++k) {
        int   bs = 0;
        float bdv = hd[0];
        int   biv = hi[0];
        #pragma unroll
        for (int s = 1; s < KSEG; ++s) {
            if (hd[s] < bdv || (hd[s] == bdv && hi[s] < biv)) {
                bdv = hd[s]; biv = hi[s]; bs = s;
            }
        }
        g_knn[m*KNN_K + k] = biv;
        int np = ++pt[bs];
        if (np < KNN_K) {
            hd[bs] = dsrc[bs*KNN_K + np];
            hi[bs] = isrc[bs*KNN_K + np];
        } else {
            hd[bs] = CUDART_INF_F; hi[bs] = 0x7FFFFFFF;
        }
    }
}

// ---------------------------------------------------------------------------
// Kernel 4: gather + linear + LayerNorm + ReLU + max over K.
// ---------------------------------------------------------------------------
__global__ __launch_bounds__(256)
void head_kernel(const float* __restrict__ p, const float* __restrict__ x,
                 const float* __restrict__ W, const float* __restrict__ gamma,
                 const float* __restrict__ beta, float* __restrict__ out) {
    __shared__ __align__(16) float sW[(3+CIN)*COUT];
    __shared__ __align__(16) float sFx[8][CIN];

    const int tid  = threadIdx.x;
    const int lane = tid & 31;
    const int w    = tid >> 5;

    for (int i = tid; i < (3+CIN)*COUT; i += 256) sW[i] = W[i];

    const int m = blockIdx.x * 8 + w;
    const int b = m >> 12;
    const float* pb = p + (size_t)b * NPB * 3;
    const float* xb = x + (size_t)b * NPB * CIN;

    const float qx = out[3*m+0], qy = out[3*m+1], qz = out[3*m+2];
    const float4 gv = ((const float4*)gamma)[lane];
    const float4 bv = ((const float4*)beta)[lane];
    int myidx = g_knn[m*KNN_K + (lane & 15)];
    __syncthreads();

    float mx0 = -CUDART_INF_F, mx1 = -CUDART_INF_F,
          mx2 = -CUDART_INF_F, mx3 = -CUDART_INF_F;

    for (int k = 0; k < KNN_K; ++k) {
        int idx = __shfl_sync(0xffffffffu, myidx, k);
        float2 xv = ((const float2*)(xb + (size_t)idx * CIN))[lane];
        ((float2*)sFx[w])[lane] = xv;
        float rx = pb[3*idx+0] - qx;
        float ry = pb[3*idx+1] - qy;
        float rz = pb[3*idx+2] - qz;
        __syncwarp();

        float a0, a1, a2, a3;
        {
            float4 w0 = *(const float4*)(sW + 0*COUT + lane*4);
            float4 w1 = *(const float4*)(sW + 1*COUT + lane*4);
            float4 w2 = *(const float4*)(sW + 2*COUT + lane*4);
            a0 = rx*w0.x; a1 = rx*w0.y; a2 = rx*w0.z; a3 = rx*w0.w;
            a0 = fmaf(ry, w1.x, a0); a1 = fmaf(ry, w1.y, a1);
            a2 = fmaf(ry, w1.z, a2); a3 = fmaf(ry, w1.w, a3);
            a0 = fmaf(rz, w2.x, a0); a1 = fmaf(rz, w2.y, a1);
            a2 = fmaf(rz, w2.z, a2); a3 = fmaf(rz, w2.w, a3);
        }
        #pragma unroll
        for (int c = 0; c < CIN; ++c) {
            float f = sFx[w][c];
            float4 wv = *(const float4*)(sW + (c+3)*COUT + lane*4);
            a0 = fmaf(f, wv.x, a0); a1 = fmaf(f, wv.y, a1);
            a2 = fmaf(f, wv.z, a2); a3 = fmaf(f, wv.w, a3);
        }
        float s = (a0 + a1) + (a2 + a3);
        #pragma unroll
        for (int o = 16; o; o >>= 1) s += __shfl_xor_sync(0xffffffffu, s, o);
        float mu = s * (1.0f/128.0f);
        float t0 = a0 - mu, t1 = a1 - mu, t2 = a2 - mu, t3 = a3 - mu;
        float v = (t0*t0 + t1*t1) + (t2*t2 + t3*t3);
        #pragma unroll
        for (int o = 16; o; o >>= 1) v += __shfl_xor_sync(0xffffffffu, v, o);
        float rs = rsqrtf(v * (1.0f/128.0f) + 1e-5f);
        float h0 = fmaf(t0*rs, gv.x, bv.x);
        float h1 = fmaf(t1*rs, gv.y, bv.y);
        float h2 = fmaf(t2*rs, gv.z, bv.z);
        float h3 = fmaf(t3*rs, gv.w, bv.w);
        mx0 = fmaxf(mx0, fmaxf(h0, 0.0f));
        mx1 = fmaxf(mx1, fmaxf(h1, 0.0f));
        mx2 = fmaxf(mx2, fmaxf(h2, 0.0f));
        mx3 = fmaxf(mx3, fmaxf(h3, 0.0f));
        __syncwarp();
    }

    float4 res = make_float4(mx0, mx1, mx2, mx3);
    ((float4*)(out + NP_SZ))[(size_t)m*32 + lane] = res;
}

// ---------------------------------------------------------------------------
// Launch
// ---------------------------------------------------------------------------
extern "C" void kernel_launch(void* const* d_in, const int* in_sizes, int n_in,
                              void* d_out, int out_size) {
    const float* p     = (const float*)d_in[0];
    const float* x     = (const float*)d_in[1];
    const float* W     = (const float*)d_in[3];
    const float* gamma = (const float*)d_in[4];
    const float* beta  = (const float*)d_in[5];
    float* out = (float*)d_out;

    const int sort_smem = NPB * (int)sizeof(unsigned);                                // 64 KB
    const int fps_smem  = 3*NPB*(int)sizeof(float) + NPB*(int)sizeof(unsigned short); // 224 KB
    cudaFuncSetAttribute(sort_kernel, cudaFuncAttributeMaxDynamicSharedMemorySize, sort_smem);
    cudaFuncSetAttribute(fps_kernel,  cudaFuncAttributeMaxDynamicSharedMemorySize, fps_smem);

    prep_kernel<<<(NTOT + 255) / 256, 256>>>(p, out);
    sort_kernel<<<BB, 1024, sort_smem>>>(p);
    fps_kernel<<<BB, 1024, fps_smem>>>(p, out);
    knn_part<<<dim3(MTOT/128, KSEG), 128>>>(out);
    knn_merge<<<MTOT/128, 128>>>();
    head_kernel<<<MTOT / 8, 256>>>(p, x, W, gamma, beta, out);
}

// round 17
// speedup vs baseline: 1.3011x; 1.0163x over previous
#include <cuda_runtime.h>
#include <math_constants.h>
#include <cstddef>

// Problem constants (fixed shapes)
#define NTOT   32768
#define NPB    16384
#define BB     2
#define MPB    4096
#define MTOT   (BB*MPB)        // 8192
#define KNN_K  16
#define CIN    64
#define COUT   128
#define NP_SZ  (MTOT*3)
#define NX_SZ  (MTOT*COUT)
#define KSEG   8
#define SEGN   (NPB/KSEG)      // 2048

// Scratch (device globals; no allocation allowed)
__device__ float4 g_p4[NTOT];
__device__ int    g_knn[MTOT*KNN_K];
__device__ int    g_sortidx[NTOT];
__device__ float  g_kd[MTOT*KSEG*KNN_K];
__device__ int    g_ki[MTOT*KSEG*KNN_K];

// ---------------------------------------------------------------------------
// Kernel 1: precompute point norms for KNN; write n_o outputs.
// ---------------------------------------------------------------------------
__global__ void prep_kernel(const float* __restrict__ p, float* __restrict__ out) {
    int i = blockIdx.x * blockDim.x + threadIdx.x;
    if (i < NTOT) {
        float px = p[3*i+0], py = p[3*i+1], pz = p[3*i+2];
        float pn = (px*px + py*py) + pz*pz;
        g_p4[i] = make_float4(px, py, pz, pn);
    }
    if (i == 0) {
        out[NP_SZ + NX_SZ + 0] = (float)MPB;
        out[NP_SZ + NX_SZ + 1] = (float)(2*MPB);
    }
}

// ---------------------------------------------------------------------------
// Kernel 1b: Morton sort (bitonic in SMEM), one CTA per batch.
// ---------------------------------------------------------------------------
__device__ __forceinline__ unsigned spread3(unsigned v) {
    v &= 0x3FFu;
    v = (v | (v << 16)) & 0x030000FFu;
    v = (v | (v << 8))  & 0x0300F00Fu;
    v = (v | (v << 4))  & 0x030C30C3u;
    v = (v | (v << 2))  & 0x09249249u;
    return v;
}

extern __shared__ unsigned sort_sm[];

__global__ __launch_bounds__(1024, 1)
void sort_kernel(const float* __restrict__ p) {
    unsigned* keys = sort_sm;
    __shared__ float smn[3][32], smx[3][32];
    __shared__ float s_mn[3], s_sc[3];

    const int b = blockIdx.x, t = threadIdx.x;
    const int lane = t & 31, warp = t >> 5;
    const float* pb = p + (size_t)b * NPB * 3;

    float mn[3] = { CUDART_INF_F,  CUDART_INF_F,  CUDART_INF_F};
    float mx[3] = {-CUDART_INF_F, -CUDART_INF_F, -CUDART_INF_F};
    #pragma unroll
    for (int j = 0; j < 16; ++j) {
        int pos = t + j*1024;
        #pragma unroll
        for (int d = 0; d < 3; ++d) {
            float v = pb[3*pos+d];
            mn[d] = fminf(mn[d], v); mx[d] = fmaxf(mx[d], v);
        }
    }
    #pragma unroll
    for (int d = 0; d < 3; ++d) {
        #pragma unroll
        for (int o = 16; o; o >>= 1) {
            mn[d] = fminf(mn[d], __shfl_xor_sync(0xffffffffu, mn[d], o));
            mx[d] = fmaxf(mx[d], __shfl_xor_sync(0xffffffffu, mx[d], o));
        }
        if (lane == 0) { smn[d][warp] = mn[d]; smx[d][warp] = mx[d]; }
    }
    __syncthreads();
    if (warp == 0) {
        #pragma unroll
        for (int d = 0; d < 3; ++d) {
            float a = smn[d][lane], c = smx[d][lane];
            #pragma unroll
            for (int o = 16; o; o >>= 1) {
                a = fminf(a, __shfl_xor_sync(0xffffffffu, a, o));
                c = fmaxf(c, __shfl_xor_sync(0xffffffffu, c, o));
            }
            if (lane == 0) {
                s_mn[d] = a;
                s_sc[d] = 63.999f / fmaxf(c - a, 1e-12f);
            }
        }
    }
    __syncthreads();
    const float mnx = s_mn[0], mny = s_mn[1], mnz = s_mn[2];
    const float scx = s_sc[0], scy = s_sc[1], scz = s_sc[2];

    #pragma unroll
    for (int j = 0; j < 16; ++j) {
        int pos = t + j*1024;
        unsigned cx = (unsigned)min(63, max(0, (int)((pb[3*pos+0]-mnx)*scx)));
        unsigned cy = (unsigned)min(63, max(0, (int)((pb[3*pos+1]-mny)*scy)));
        unsigned cz = (unsigned)min(63, max(0, (int)((pb[3*pos+2]-mnz)*scz)));
        unsigned code = spread3(cx) | (spread3(cy) << 1) | (spread3(cz) << 2);
        keys[pos] = (code << 14) | (unsigned)pos;
    }
    __syncthreads();

    for (int k = 2; k <= NPB; k <<= 1) {
        for (int j = k >> 1; j > 0; j >>= 1) {
            #pragma unroll
            for (int q = 0; q < NPB/2/1024; ++q) {
                int t2 = t + q*1024;
                int i  = 2*t2 - (t2 & (j-1));
                int ix = i + j;
                bool up = ((i & k) == 0);
                unsigned a = keys[i], c = keys[ix];
                if ((a > c) == up) { keys[i] = c; keys[ix] = a; }
            }
            __syncthreads();
        }
    }

    #pragma unroll
    for (int j = 0; j < 16; ++j) {
        int pos = t + j*1024;
        g_sortidx[b*NPB + pos] = (int)(keys[pos] & 0x3FFFu);
    }
}

// ---------------------------------------------------------------------------
// Kernel 2: FPS with exact chunk pruning (R12/R15 structure, verbatim).
// Tail chunks (radius > 1.5*mean) packed into the lowest warps; core keeps
// Morton order. Thread owns chunk q: sphere/threshold/cached key + dist[16]
// in registers. Coords as float2(x,y)+float(z) in transposed SMEM
// (addr = (pos&15)*1024 + (pos>>4)); sid stores PRE-FLIPPED original index.
// Two-pass rescan. Selection rule identical -> bit-exact.
// ---------------------------------------------------------------------------
extern __shared__ float fps_sm[];

__global__ __launch_bounds__(1024, 1)
void fps_kernel(const float* __restrict__ p, float* __restrict__ out) {
    float2* sxy = (float2*)fps_sm;                          // 128 KB
    float*  sz  = fps_sm + 2*NPB;                           // 64 KB
    unsigned short* sid = (unsigned short*)(fps_sm + 3*NPB);// 32 KB
    int* scratch = (int*)(fps_sm + 3*NPB);      // overlays sid; used pre-fill

    __shared__ unsigned long long s_k[2][32];
    __shared__ float s_wsum[32];
    __shared__ int   s_wcnt[32];
    __shared__ int   s_woff[32];
    __shared__ float s_theta;
    __shared__ int   s_B;

    const int b = blockIdx.x, t = threadIdx.x;
    const int lane = t & 31, warp = t >> 5;
    const float* pb = p + (size_t)b * NPB * 3;
    const int* sidg = g_sortidx + b*NPB;

    // 1. coords into transposed SMEM
    #pragma unroll
    for (int j = 0; j < 16; ++j) {
        int pos = t + j*1024;
        int oi  = sidg[pos];
        int addr = (pos & 15)*1024 + (pos >> 4);
        sxy[addr] = make_float2(pb[3*oi+0], pb[3*oi+1]);
        sz[addr]  = pb[3*oi+2];
    }
    if (t == 0) {
        float* orow = out + (size_t)b * MPB * 3;
        orow[0] = pb[0]; orow[1] = pb[1]; orow[2] = pb[2];
    }
    __syncthreads();

    // 2. radius of the ALIGNED chunk t (partition decision)
    float rt;
    {
        float mnx = CUDART_INF_F, mny = CUDART_INF_F, mnz = CUDART_INF_F;
        float mxx = -CUDART_INF_F, mxy = -CUDART_INF_F, mxz = -CUDART_INF_F;
        #pragma unroll
        for (int j = 0; j < 16; ++j) {
            int addr = j*1024 + t;
            float2 xy = sxy[addr];
            float z = sz[addr];
            mnx = fminf(mnx, xy.x); mxx = fmaxf(mxx, xy.x);
            mny = fminf(mny, xy.y); mxy = fmaxf(mxy, xy.y);
            mnz = fminf(mnz, z);    mxz = fmaxf(mxz, z);
        }
        float ax = 0.5f*(mnx+mxx), ay = 0.5f*(mny+mxy), az = 0.5f*(mnz+mxz);
        float r2 = 0.0f;
        #pragma unroll
        for (int j = 0; j < 16; ++j) {
            int addr = j*1024 + t;
            float2 xy = sxy[addr];
            float dx = xy.x-ax, dy = xy.y-ay, dz = sz[addr]-az;
            r2 = fmaxf(r2, dx*dx + dy*dy + dz*dz);
        }
        rt = sqrtf(r2);
    }
    // mean radius -> theta
    {
        float rs = rt;
        #pragma unroll
        for (int o = 16; o; o >>= 1) rs += __shfl_xor_sync(0xffffffffu, rs, o);
        if (lane == 0) s_wsum[warp] = rs;
    }
    __syncthreads();
    if (warp == 0) {
        float v = s_wsum[lane];
        #pragma unroll
        for (int o = 16; o; o >>= 1) v += __shfl_xor_sync(0xffffffffu, v, o);
        if (lane == 0) s_theta = 1.5f * (v * (1.0f/1024.0f));
    }
    __syncthreads();

    // 3. partition: big chunks -> slots [0,B), core chunks keep order after
    bool big = rt > s_theta;
    unsigned wb = __ballot_sync(0xffffffffu, big);
    if (lane == 0) s_wcnt[warp] = __popc(wb);
    __syncthreads();
    if (warp == 0) {
        int c = s_wcnt[lane];
        int inc = c;
        #pragma unroll
        for (int o = 1; o < 32; o <<= 1) {
            int n = __shfl_up_sync(0xffffffffu, inc, o);
            if (lane >= o) inc += n;
        }
        s_woff[lane] = inc - c;
        if (lane == 31) s_B = inc;
    }
    __syncthreads();
    int bigsBefore = s_woff[warp] + __popc(wb & ((1u << lane) - 1u));
    int slot = big ? bigsBefore : (s_B + (t - bigsBefore));
    scratch[slot] = t;
    __syncthreads();
    const int q = scratch[t];          // chunk owned by this thread
    __syncthreads();

    // 4. fill sid with PRE-FLIPPED original index (overwrites scratch)
    #pragma unroll
    for (int j = 0; j < 16; ++j) {
        int pos = t + j*1024;
        int addr = (pos & 15)*1024 + (pos >> 4);
        sid[addr] = (unsigned short)(sidg[pos] ^ 0x3FFF);
    }
    __syncthreads();

    // 5. sphere for chunk q
    float c0x, c0y, c0z, r;
    {
        float mnx = CUDART_INF_F, mny = CUDART_INF_F, mnz = CUDART_INF_F;
        float mxx = -CUDART_INF_F, mxy = -CUDART_INF_F, mxz = -CUDART_INF_F;
        #pragma unroll
        for (int j = 0; j < 16; ++j) {
            int addr = j*1024 + q;
            float2 xy = sxy[addr];
            float z = sz[addr];
            mnx = fminf(mnx, xy.x); mxx = fmaxf(mxx, xy.x);
            mny = fminf(mny, xy.y); mxy = fmaxf(mxy, xy.y);
            mnz = fminf(mnz, z);    mxz = fmaxf(mxz, z);
        }
        c0x = 0.5f*(mnx+mxx); c0y = 0.5f*(mny+mxy); c0z = 0.5f*(mnz+mxz);
        float r2 = 0.0f;
        #pragma unroll
        for (int j = 0; j < 16; ++j) {
            int addr = j*1024 + q;
            float2 xy = sxy[addr];
            float dx = xy.x-c0x, dy = xy.y-c0y, dz = sz[addr]-c0z;
            r2 = fmaxf(r2, dx*dx + dy*dy + dz*dz);
        }
        r = sqrtf(r2) * 1.0002f + 1e-12f;
    }

    float dist[16];
    #pragma unroll
    for (int j = 0; j < 16; ++j) dist[j] = CUDART_INF_F;

    unsigned long long mykey =
        ((unsigned long long)__float_as_uint(CUDART_INF_F) << 32) | (unsigned)(q << 4);
    float tr = CUDART_INF_F;
    unsigned long long wkey = 0;

    float cx = pb[0], cy = pb[1], cz = pb[2];
    const unsigned qbase = (unsigned)(q << 4);

    for (int i = 1; i < MPB; ++i) {
        float ddx = cx - c0x, ddy = cy - c0y, ddz = cz - c0z;
        float L2c = ddx*ddx + ddy*ddy + ddz*ddz;
        bool active = !(L2c > tr);

        if (active) {
            float nm = -CUDART_INF_F;
            #pragma unroll
            for (int j = 0; j < 16; ++j) {
                int addr = j*1024 + q;
                float2 xy = sxy[addr];
                float dx = xy.x - cx;
                float dy = xy.y - cy;
                float dz = sz[addr] - cz;
                float d = __fadd_rn(__fadd_rn(__fmul_rn(dx,dx), __fmul_rn(dy,dy)),
                                    __fmul_rn(dz,dz));
                float nd = fminf(dist[j], d);
                dist[j] = nd;
                nm = fmaxf(nm, nd);
            }
            unsigned lkbest = 0u;
            #pragma unroll
            for (int j = 0; j < 16; ++j) {
                if (dist[j] == nm) {
                    int addr = j*1024 + q;
                    unsigned lk = ((unsigned)sid[addr] << 14) | (qbase + (unsigned)j);
                    lkbest = max(lkbest, lk);
                }
            }
            mykey = ((unsigned long long)__float_as_uint(nm) << 32) | lkbest;
            float rr = r + sqrtf(nm);
            tr = rr*rr*1.0002f;
        }
        if (__ballot_sync(0xffffffffu, active)) {
            unsigned hi = (unsigned)(mykey >> 32);
            unsigned lo = (unsigned)mykey;
            unsigned hm = __reduce_max_sync(0xffffffffu, hi);
            unsigned cd = (hi == hm) ? lo : 0u;
            unsigned lm = __reduce_max_sync(0xffffffffu, cd);
            wkey = ((unsigned long long)hm << 32) | lm;
        }
        if (lane == 0)
            s_k[i & 1][warp] = wkey;
        __syncthreads();

        unsigned long long kk = s_k[i & 1][lane];
        unsigned h2  = (unsigned)(kk >> 32);
        unsigned lo2 = (unsigned)kk;
        unsigned hb  = __reduce_max_sync(0xffffffffu, h2);
        unsigned c2  = (h2 == hb) ? lo2 : 0u;
        unsigned lob = __reduce_max_sync(0xffffffffu, c2);
        int wpos = (int)(lob & 0x3FFFu);
        int waddr = (wpos & 15)*1024 + (wpos >> 4);
        float2 wxy = sxy[waddr];
        cx = wxy.x; cy = wxy.y; cz = sz[waddr];
        if (t == 0) {
            float* orow = out + ((size_t)b * MPB + i) * 3;
            orow[0] = cx; orow[1] = cy; orow[2] = cz;
        }
    }
}

// ---------------------------------------------------------------------------
// Kernel 3a: segmented KNN (top-16 per 2048-pt segment per query).
// Transformed distance d2' = 0.5*|p|^2 - q.p (per-query monotone).
// Fewer, longer segments: the warp-correlated "fill phase" (~first 512
// points) is amortized over 2048 points instead of 1024.
// ---------------------------------------------------------------------------
__global__ __launch_bounds__(128)
void knn_part(const float* __restrict__ out_np) {
    __shared__ float4 tile[SEGN];       // 32 KB
    const int m = blockIdx.x * 128 + threadIdx.x;
    const int s = blockIdx.y;
    const int b = m >> 12;
    const int base = (b << 14) + s * SEGN;

    const float qx = out_np[3*m+0];
    const float qy = out_np[3*m+1];
    const float qz = out_np[3*m+2];

    #pragma unroll
    for (int i = 0; i < SEGN/128; ++i)
        tile[threadIdx.x + i*128] = g_p4[base + threadIdx.x + i*128];
    __syncthreads();

    float bd[KNN_K];
    int   bi[KNN_K];
    #pragma unroll
    for (int k = 0; k < KNN_K; ++k) { bd[k] = CUDART_INF_F; bi[k] = 0x7FFFFFFF; }

    #pragma unroll 4
    for (int tt = 0; tt < SEGN; ++tt) {
        float4 pp = tile[tt];
        float dot = qx*pp.x + qy*pp.y + qz*pp.z;
        float d2  = fmaf(0.5f, pp.w, -dot);
        if (d2 < bd[KNN_K-1]) {
            bd[KNN_K-1] = d2; bi[KNN_K-1] = s*SEGN + tt;
            #pragma unroll
            for (int k = KNN_K-1; k > 0; --k) {
                if (bd[k] < bd[k-1]) {
                    float td = bd[k]; bd[k] = bd[k-1]; bd[k-1] = td;
                    int   ti = bi[k]; bi[k] = bi[k-1]; bi[k-1] = ti;
                }
            }
        }
    }
    float* od = g_kd + ((size_t)m*KSEG + s) * KNN_K;
    int*   oi = g_ki + ((size_t)m*KSEG + s) * KNN_K;
    #pragma unroll
    for (int k = 0; k < KNN_K; ++k) { od[k] = bd[k]; oi[k] = bi[k]; }
}

// ---------------------------------------------------------------------------
// Kernel 3b: 8-way merge of sorted per-segment lists.
// ---------------------------------------------------------------------------
__global__ __launch_bounds__(128)
void knn_merge() {
    const int m = blockIdx.x * 128 + threadIdx.x;
    const float* dsrc = g_kd + (size_t)m * KSEG * KNN_K;
    const int*   isrc = g_ki + (size_t)m * KSEG * KNN_K;

    int   pt[KSEG];
    float hd[KSEG];
    int   hi[KSEG];
    #pragma unroll
    for (int s = 0; s < KSEG; ++s) {
        pt[s] = 0;
        hd[s] = dsrc[s*KNN_K];
        hi[s] = isrc[s*KNN_K];
    }
    #pragma unroll
    for (int k = 0; k < KNN_K; ++k) {
        int   bs = 0;
        float bdv = hd[0];
        int   biv = hi[0];
        #pragma unroll
        for (int s = 1; s < KSEG; ++s) {
            if (hd[s] < bdv || (hd[s] == bdv && hi[s] < biv)) {
                bdv = hd[s]; biv = hi[s]; bs = s;
            }
        }
        g_knn[m*KNN_K + k] = biv;
        int np = ++pt[bs];
        if (np < KNN_K) {
            hd[bs] = dsrc[bs*KNN_K + np];
            hi[bs] = isrc[bs*KNN_K + np];
        } else {
            hd[bs] = CUDART_INF_F; hi[bs] = 0x7FFFFFFF;
        }
    }
}

// ---------------------------------------------------------------------------
// Kernel 4: gather + linear + LayerNorm + ReLU + max over K.
// ---------------------------------------------------------------------------
__global__ __launch_bounds__(256)
void head_kernel(const float* __restrict__ p, const float* __restrict__ x,
                 const float* __restrict__ W, const float* __restrict__ gamma,
                 const float* __restrict__ beta, float* __restrict__ out) {
    __shared__ __align__(16) float sW[(3+CIN)*COUT];
    __shared__ __align__(16) float sFx[8][CIN];

    const int tid  = threadIdx.x;
    const int lane = tid & 31;
    const int w    = tid >> 5;

    for (int i = tid; i < (3+CIN)*COUT; i += 256) sW[i] = W[i];

    const int m = blockIdx.x * 8 + w;
    const int b = m >> 12;
    const float* pb = p + (size_t)b * NPB * 3;
    const float* xb = x + (size_t)b * NPB * CIN;

    const float qx = out[3*m+0], qy = out[3*m+1], qz = out[3*m+2];
    const float4 gv = ((const float4*)gamma)[lane];
    const float4 bv = ((const float4*)beta)[lane];
    int myidx = g_knn[m*KNN_K + (lane & 15)];
    __syncthreads();

    float mx0 = -CUDART_INF_F, mx1 = -CUDART_INF_F,
          mx2 = -CUDART_INF_F, mx3 = -CUDART_INF_F;

    for (int k = 0; k < KNN_K; ++k) {
        int idx = __shfl_sync(0xffffffffu, myidx, k);
        float2 xv = ((const float2*)(xb + (size_t)idx * CIN))[lane];
        ((float2*)sFx[w])[lane] = xv;
        float rx = pb[3*idx+0] - qx;
        float ry = pb[3*idx+1] - qy;
        float rz = pb[3*idx+2] - qz;
        __syncwarp();

        float a0, a1, a2, a3;
        {
            float4 w0 = *(const float4*)(sW + 0*COUT + lane*4);
            float4 w1 = *(const float4*)(sW + 1*COUT + lane*4);
            float4 w2 = *(const float4*)(sW + 2*COUT + lane*4);
            a0 = rx*w0.x; a1 = rx*w0.y; a2 = rx*w0.z; a3 = rx*w0.w;
            a0 = fmaf(ry, w1.x, a0); a1 = fmaf(ry, w1.y, a1);
            a2 = fmaf(ry, w1.z, a2); a3 = fmaf(ry, w1.w, a3);
            a0 = fmaf(rz, w2.x, a0); a1 = fmaf(rz, w2.y, a1);
            a2 = fmaf(rz, w2.z, a2); a3 = fmaf(rz, w2.w, a3);
        }
        #pragma unroll
        for (int c = 0; c < CIN; ++c) {
            float f = sFx[w][c];
            float4 wv = *(const float4*)(sW + (c+3)*COUT + lane*4);
            a0 = fmaf(f, wv.x, a0); a1 = fmaf(f, wv.y, a1);
            a2 = fmaf(f, wv.z, a2); a3 = fmaf(f, wv.w, a3);
        }
        float s = (a0 + a1) + (a2 + a3);
        #pragma unroll
        for (int o = 16; o; o >>= 1) s += __shfl_xor_sync(0xffffffffu, s, o);
        float mu = s * (1.0f/128.0f);
        float t0 = a0 - mu, t1 = a1 - mu, t2 = a2 - mu, t3 = a3 - mu;
        float v = (t0*t0 + t1*t1) + (t2*t2 + t3*t3);
        #pragma unroll
        for (int o = 16; o; o >>= 1) v += __shfl_xor_sync(0xffffffffu, v, o);
        float rs = rsqrtf(v * (1.0f/128.0f) + 1e-5f);
        float h0 = fmaf(t0*rs, gv.x, bv.x);
        float h1 = fmaf(t1*rs, gv.y, bv.y);
        float h2 = fmaf(t2*rs, gv.z, bv.z);
        float h3 = fmaf(t3*rs, gv.w, bv.w);
        mx0 = fmaxf(mx0, fmaxf(h0, 0.0f));
        mx1 = fmaxf(mx1, fmaxf(h1, 0.0f));
        mx2 = fmaxf(mx2, fmaxf(h2, 0.0f));
        mx3 = fmaxf(mx3, fmaxf(h3, 0.0f));
        __syncwarp();
    }

    float4 res = make_float4(mx0, mx1, mx2, mx3);
    ((float4*)(out + NP_SZ))[(size_t)m*32 + lane] = res;
}

// ---------------------------------------------------------------------------
// Launch
// ---------------------------------------------------------------------------
extern "C" void kernel_launch(void* const* d_in, const int* in_sizes, int n_in,
                              void* d_out, int out_size) {
    const float* p     = (const float*)d_in[0];
    const float* x     = (const float*)d_in[1];
    const float* W     = (const float*)d_in[3];
    const float* gamma = (const float*)d_in[4];
    const float* beta  = (const float*)d_in[5];
    float* out = (float*)d_out;

    const int sort_smem = NPB * (int)sizeof(unsigned);                                // 64 KB
    const int fps_smem  = 3*NPB*(int)sizeof(float) + NPB*(int)sizeof(unsigned short); // 224 KB
    cudaFuncSetAttribute(sort_kernel, cudaFuncAttributeMaxDynamicSharedMemorySize, sort_smem);
    cudaFuncSetAttribute(fps_kernel,  cudaFuncAttributeMaxDynamicSharedMemorySize, fps_smem);

    prep_kernel<<<(NTOT + 255) / 256, 256>>>(p, out);
    sort_kernel<<<BB, 1024, sort_smem>>>(p);
    fps_kernel<<<BB, 1024, fps_smem>>>(p, out);
    knn_part<<<dim3(MTOT/128, KSEG), 128>>>(out);
    knn_merge<<<MTOT/128, 128>>>();
    head_kernel<<<MTOT / 8, 256>>>(p, x, W, gamma, beta, out);
}